// round 5
// baseline (speedup 1.0000x reference)
#include <cuda_runtime.h>
#include <cuda_bf16.h>

// x viewed as [T=16384 tokens][H=32 heads][D=128 dims], fp32.
// For each (t, d): 32-point Walsh-Hadamard across h, * 1/sqrt(32).
// Each thread now owns TWO consecutive d (a float2 column pair):
// warp access at fixed h = 32 lanes * 8B = 256B contiguous -> coalesced.

#define NUM_HEADS 32
#define HEAD_DIM  128
#define PAIRS     (HEAD_DIM / 2)   // 64 float2 slots per token row

__global__ __launch_bounds__(256) void had32_kernel_v2(
    const float* __restrict__ x, float* __restrict__ out, long n_pairs)
{
    long idx = (long)blockIdx.x * blockDim.x + threadIdx.x;
    if (idx >= n_pairs) return;

    long t = idx >> 6;          // idx / 64
    int  p = (int)(idx & 63);   // float2 slot within head_dim

    const float2* __restrict__ in_base  =
        (const float2*)(x   + (t << 12)) + p;   // t*4096 floats
    float2*       __restrict__ out_base =
        (float2*)(out + (t << 12)) + p;

    float2 v[NUM_HEADS];
    #pragma unroll
    for (int h = 0; h < NUM_HEADS; ++h)
        v[h] = __ldcs(in_base + (h << 6));   // stride 64 float2 = 128 floats

    // In-place fast WHT (Sylvester ordering), on both lanes of the float2.
    #pragma unroll
    for (int len = 1; len < NUM_HEADS; len <<= 1) {
        #pragma unroll
        for (int i = 0; i < NUM_HEADS; ++i) {
            if ((i & len) == 0) {
                float2 a = v[i];
                float2 b = v[i + len];
                v[i].x       = a.x + b.x;
                v[i].y       = a.y + b.y;
                v[i + len].x = a.x - b.x;
                v[i + len].y = a.y - b.y;
            }
        }
    }

    const float scale = 0.17677669529663687f;  // 1/sqrt(32)
    #pragma unroll
    for (int h = 0; h < NUM_HEADS; ++h) {
        float2 r;
        r.x = v[h].x * scale;
        r.y = v[h].y * scale;
        __stcs(out_base + (h << 6), r);
    }
}

extern "C" void kernel_launch(void* const* d_in, const int* in_sizes, int n_in,
                              void* d_out, int out_size)
{
    const float* x = (const float*)d_in[0];
    float* out = (float*)d_out;

    long n = (long)in_sizes[0];              // total elements
    long n_pairs = n / (NUM_HEADS * 2);      // one thread per float2 column pair

    int threads = 256;
    long blocks = (n_pairs + threads - 1) / threads;
    had32_kernel_v2<<<(unsigned)blocks, threads>>>(x, out, n_pairs);
}

// round 6
// speedup vs baseline: 1.0784x; 1.0784x over previous
#include <cuda_runtime.h>
#include <cuda_bf16.h>

// x viewed as [T=16384 tokens][H=32 heads][D=128 dims], fp32.
// For each (t, d): 32-point Walsh-Hadamard across h, * 1/sqrt(32).
// One thread per (t, d) column; consecutive lanes take consecutive d,
// so every strided access is a full 128B sector per warp (coalesced).
// Scalar accesses keep regs at ~40 -> high occupancy -> enough MLP to
// saturate HBM (R2's float2 variant dropped occupancy and lost 10% DRAM).

#define NUM_HEADS 32
#define HEAD_DIM  128

__global__ __launch_bounds__(256) void had32_kernel_v3(
    const float* __restrict__ x, float* __restrict__ out, long n_cols)
{
    long col = (long)blockIdx.x * blockDim.x + threadIdx.x;
    if (col >= n_cols) return;

    long t = col >> 7;          // col / 128
    int  d = (int)(col & 127);  // col % 128

    const float* __restrict__ in_base  = x   + (t << 12) + d;  // t*4096 + d
    float*       __restrict__ out_base = out + (t << 12) + d;

    float v[NUM_HEADS];
    #pragma unroll
    for (int h = 0; h < NUM_HEADS; ++h)
        v[h] = __ldcs(in_base + (h << 7));   // evict-first: zero-reuse stream

    // In-place fast WHT, Sylvester ordering (matches reference butterfly).
    #pragma unroll
    for (int len = 1; len < NUM_HEADS; len <<= 1) {
        #pragma unroll
        for (int i = 0; i < NUM_HEADS; ++i) {
            if ((i & len) == 0) {
                float a = v[i];
                float b = v[i + len];
                v[i]       = a + b;
                v[i + len] = a - b;
            }
        }
    }

    const float scale = 0.17677669529663687f;  // 1/sqrt(32)
    #pragma unroll
    for (int h = 0; h < NUM_HEADS; ++h)
        __stcs(out_base + (h << 7), v[h] * scale);
}

extern "C" void kernel_launch(void* const* d_in, const int* in_sizes, int n_in,
                              void* d_out, int out_size)
{
    const float* x = (const float*)d_in[0];
    float* out = (float*)d_out;

    long n = (long)in_sizes[0];          // total elements (4*4096*4096)
    long n_cols = n / NUM_HEADS;         // one thread per (token, dim) column

    int threads = 256;
    long blocks = (n_cols + threads - 1) / threads;
    had32_kernel_v3<<<(unsigned)blocks, threads>>>(x, out, n_cols);
}